// round 16
// baseline (speedup 1.0000x reference)
#include <cuda_runtime.h>
#include <cuda_bf16.h>
#include <cstdint>

#define DEV_INLINE __device__ __forceinline__
constexpr int BATCH=256, DIMC=384, NTOK=49;
constexpr int T2=BATCH*NTOK;            // 12544 dense tokens = 98*128
constexpr int HEADS=8, DVAL=128, DHCH=1024, HID=1536, QKVC=1536;
typedef __nv_bfloat16 bf16;
typedef __nv_bfloat162 bf162;

__device__ bf16  g_wqkv[QKVC*DIMC], g_wproj[DIMC*DHCH];
__device__ bf16  g_wfc1[HID*DIMC],  g_wfc2[DIMC*HID];
__device__ float g_bqkv[QKVC];
__device__ bf16  g_xt [DIMC*T2];
__device__ bf16  g_qkv[QKVC*T2], g_vloc[DHCH*T2], g_attn[DHCH*T2];
__device__ float g_yf [DIMC*T2];
__device__ bf16  g_yb [DIMC*T2], g_h1[HID*T2], g_h2[HID*T2];
__device__ bf16  g_biasx[HEADS*49*52];
__device__ bf16  g_S[(size_t)BATCH*HEADS*64*64];
__device__ bf16  g_P[(size_t)BATCH*HEADS*64*64];   // rows n>=49 stay zero

DEV_INLINE uint32_t smem_u32(const void* p){ return (uint32_t)__cvta_generic_to_shared(p); }
DEV_INLINE void cp16(void* s, const void* g){
    asm volatile("cp.async.ca.shared.global [%0], [%1], 16;\n"::"r"(smem_u32(s)),"l"(g)); }
DEV_INLINE void cp_commit(){ asm volatile("cp.async.commit_group;\n"); }
DEV_INLINE void cp_wait2(){ asm volatile("cp.async.wait_group 2;\n"); }
DEV_INLINE void ldsm_x4(uint32_t r[4], uint32_t a){
    asm volatile("ldmatrix.sync.aligned.m8n8.x4.shared.b16 {%0,%1,%2,%3}, [%4];\n"
        :"=r"(r[0]),"=r"(r[1]),"=r"(r[2]),"=r"(r[3]):"r"(a)); }
DEV_INLINE void ldsm_x4_t(uint32_t r[4], uint32_t a){
    asm volatile("ldmatrix.sync.aligned.m8n8.x4.trans.shared.b16 {%0,%1,%2,%3}, [%4];\n"
        :"=r"(r[0]),"=r"(r[1]),"=r"(r[2]),"=r"(r[3]):"r"(a)); }
DEV_INLINE void mma_bf16(float c[4], const uint32_t a[4], uint32_t b0, uint32_t b1){
    asm volatile("mma.sync.aligned.m16n8k16.row.col.f32.bf16.bf16.f32 "
        "{%0,%1,%2,%3},{%4,%5,%6,%7},{%8,%9},{%0,%1,%2,%3};\n"
        :"+f"(c[0]),"+f"(c[1]),"+f"(c[2]),"+f"(c[3])
        :"r"(a[0]),"r"(a[1]),"r"(a[2]),"r"(a[3]),"r"(b0),"r"(b1)); }

// ---------------- prologue ---------------------------------------------------
constexpr int W1=256*384, W3=1024*384, WP=384*1024, WF=1536*384;
constexpr long PTOTAL=(long)W1*2+W3+WP+WF*2+1536+(long)DIMC*T2;
__global__ void prologue(const float* qw,const float* kw,const float* vw,
                         const float* qb,const float* kb,const float* vb,
                         const float* pw,const float* f1w,const float* f2w,const float* x){
    long i=(long)blockIdx.x*blockDim.x+threadIdx.x;
    if(i>=PTOTAL) return;
    if(i<W1){ g_wqkv[i]=__float2bfloat16(qw[i]); return;} i-=W1;
    if(i<W1){ g_wqkv[W1+i]=__float2bfloat16(kw[i]); return;} i-=W1;
    if(i<W3){ g_wqkv[2*W1+i]=__float2bfloat16(vw[i]); return;} i-=W3;
    if(i<WP){ g_wproj[i]=__float2bfloat16(pw[i]); return;} i-=WP;
    if(i<WF){ g_wfc1[i]=__float2bfloat16(f1w[i]); return;} i-=WF;
    if(i<WF){ g_wfc2[i]=__float2bfloat16(f2w[i]); return;} i-=WF;
    if(i<256){ g_bqkv[i]=qb[i]; return;} i-=256;
    if(i<256){ g_bqkv[256+i]=kb[i]; return;} i-=256;
    if(i<1024){ g_bqkv[512+i]=vb[i]; return;} i-=1024;
    int c=(int)(i/T2), t=(int)(i%T2);
    int img=t/49, n=t%49;
    g_xt[i]=__float2bfloat16(x[((size_t)img*DIMC+c)*49+n]);
}
__global__ void bias_expand(const float* attn_bias, const int* bias_idxs){
    int i=blockIdx.x*blockDim.x+threadIdx.x;
    if(i>=HEADS*49*52) return;
    int h=i/(49*52), r=i%(49*52), n=r/52, m=r%52;
    float v=(m<49)? attn_bias[h*49+bias_idxs[n*49+m]] : 0.f;
    g_biasx[i]=__float2bfloat16(v);
}

// ---------------- depthwise 3x3: CTA = 128 images of ONE channel -------------
template<int WHICH>
__global__ __launch_bounds__(128) void dw_kernel(
    const float* __restrict__ w9, const float* __restrict__ b9){
    __shared__ bf16 sin [128*49];
    __shared__ bf16 sout[128*49];
    const int blk=blockIdx.x, ch=blk>>1, half=blk&1;
    const int tid=threadIdx.x;
    const bf16* in  = ((WHICH==0)? (g_qkv+(size_t)512*T2) : g_h1)
                      + (size_t)ch*T2 + (size_t)half*6272;
    bf16*       out = ((WHICH==0)? g_vloc : g_h2)
                      + (size_t)ch*T2 + (size_t)half*6272;

    for(int i=tid;i<3136;i+=128) ((bf162*)sin)[i]=((const bf162*)in)[i];
    float w[9];
    #pragma unroll
    for(int k=0;k<9;k++) w[k]=__ldg(&w9[ch*9+k]);
    const float bb=__ldg(&b9[ch]);
    __syncthreads();

    const bf16* v=&sin[tid*49];
    bf16* o=&sout[tid*49];
    #pragma unroll
    for(int pi=0;pi<7;pi++){
        #pragma unroll
        for(int pj=0;pj<7;pj++){
            float s=bb;
            #pragma unroll
            for(int di=-1;di<=1;di++){
                if(pi+di<0||pi+di>6) continue;
                #pragma unroll
                for(int dj=-1;dj<=1;dj++){
                    if(pj+dj<0||pj+dj>6) continue;
                    s+=w[(di+1)*3+(dj+1)]*__bfloat162float(v[(pi+di)*7+(pj+dj)]);
                }
            }
            if(WHICH==1) s=fmaxf(s,0.f);
            o[pi*7+pj]=__float2bfloat16(s);
        }
    }
    __syncthreads();
    for(int i=tid;i<3136;i+=128) ((bf162*)out)[i]=((const bf162*)sout)[i];
}

// ---------------- unified GEMM: BM=64, BN=128, BK=32, 4-stage ----------------
enum { M_QKV=0, M_PROJ=1, M_FC1=2, M_FC2=3 };
constexpr int SA64=64*40, SB64=32*136;
constexpr int STG64=(SA64+SB64)*2;
constexpr int NSTG=4;
constexpr int G64_SMEM=NSTG*STG64;

template<int K>
DEV_INLINE void load_stage64(char* sm,int s,int k0,int m0,int t0,int tid,
                             const bf16* __restrict__ A,const bf16* __restrict__ Bm){
    bf16* sA=(bf16*)(sm+s*STG64);
    bf16* sB=(bf16*)(sm+s*STG64+SA64*2);
    { int row=tid>>2, part=tid&3;
      cp16(&sA[row*40+part*8], &A[(size_t)(m0+row)*K+k0+part*8]); }
    #pragma unroll
    for(int i=0;i<2;i++){ int c=tid+i*256, row=c>>4, part=c&15;
        cp16(&sB[row*136+part*8], &Bm[(size_t)(k0+row)*T2+t0+part*8]); }
}

template<int MODE,int K>
__global__ __launch_bounds__(256) void gemm64(
    const float* __restrict__ bias, const float* __restrict__ xres,
    const float* __restrict__ ls,   float* __restrict__ outp)
{
    extern __shared__ char sm[];
    const int m0=blockIdx.x*64, t0=blockIdx.y*128;
    const int tid=threadIdx.x, lane=tid&31, warp=tid>>5;
    const int m0w=(warp>>2)*32, n0w=(warp&3)*32;
    const int gid=lane>>2, tig=lane&3;
    const bf16 *A, *Bm;
    if constexpr(MODE==M_QKV){ A=g_wqkv; Bm=g_xt; }
    else if constexpr(MODE==M_PROJ){ A=g_wproj; Bm=g_attn; }
    else if constexpr(MODE==M_FC1){ A=g_wfc1; Bm=g_yb; }
    else { A=g_wfc2; Bm=g_h2; }

    float acc[2][4][4];
    #pragma unroll
    for(int mi=0;mi<2;mi++)
        #pragma unroll
        for(int nj=0;nj<4;nj++){ acc[mi][nj][0]=acc[mi][nj][1]=acc[mi][nj][2]=acc[mi][nj][3]=0.f; }

    constexpr int KT=K/32;
    load_stage64<K>(sm,0,0,m0,t0,tid,A,Bm);  cp_commit();
    load_stage64<K>(sm,1,32,m0,t0,tid,A,Bm); cp_commit();
    load_stage64<K>(sm,2,64,m0,t0,tid,A,Bm); cp_commit();
    for(int it=0;it<KT;++it){
        cp_wait2(); __syncthreads();
        const bf16* sA=(const bf16*)(sm+(it%NSTG)*STG64);
        const bf16* sB=(const bf16*)(sm+(it%NSTG)*STG64+SA64*2);
        #pragma unroll
        for(int kk=0;kk<32;kk+=16){
            uint32_t a[2][4], bfr[2][4];
            #pragma unroll
            for(int mi=0;mi<2;mi++)
                ldsm_x4(a[mi], smem_u32(&sA[(m0w+mi*16+(lane&15))*40+kk+((lane>>4)<<3)]));
            #pragma unroll
            for(int ni=0;ni<2;ni++)
                ldsm_x4_t(bfr[ni], smem_u32(&sB[(kk+(lane&7)+((lane>>3)&1)*8)*136+n0w+ni*16+((lane>>4)<<3)]));
            #pragma unroll
            for(int mi=0;mi<2;mi++)
                #pragma unroll
                for(int nj=0;nj<4;nj++)
                    mma_bf16(acc[mi][nj], a[mi], bfr[nj>>1][(nj&1)?2:0], bfr[nj>>1][(nj&1)?3:1]);
        }
        if(it+3<KT) load_stage64<K>(sm,(it+3)%NSTG,(it+3)*32,m0,t0,tid,A,Bm);
        cp_commit();
    }
    __syncthreads();
    bf16* sOut=(bf16*)sm;
    float bs[2][2];
    #pragma unroll
    for(int mi=0;mi<2;mi++){
        int r=m0+m0w+mi*16+gid;
        if constexpr(MODE==M_QKV){ bs[mi][0]=g_bqkv[r]; bs[mi][1]=g_bqkv[r+8]; }
        else { bs[mi][0]=bias[r]; bs[mi][1]=bias[r+8]; }
    }
    #pragma unroll
    for(int mi=0;mi<2;mi++)
        #pragma unroll
        for(int nj=0;nj<4;nj++){
            int mrow=m0w+mi*16+gid, ncol=n0w+nj*8+tig*2;
            float v0=acc[mi][nj][0]+bs[mi][0], v1=acc[mi][nj][1]+bs[mi][0];
            float v2=acc[mi][nj][2]+bs[mi][1], v3=acc[mi][nj][3]+bs[mi][1];
            if constexpr(MODE==M_FC1){ v0=fmaxf(v0,0.f); v1=fmaxf(v1,0.f); v2=fmaxf(v2,0.f); v3=fmaxf(v3,0.f); }
            *(bf162*)&sOut[mrow*136+ncol]=bf162(__float2bfloat16(v0),__float2bfloat16(v1));
            *(bf162*)&sOut[(mrow+8)*136+ncol]=bf162(__float2bfloat16(v2),__float2bfloat16(v3));
        }
    __syncthreads();

    if constexpr(MODE==M_QKV || MODE==M_FC1){
        bf16* dst = (MODE==M_QKV)? g_qkv : g_h1;
        for(int i=tid;i<4096;i+=256){
            int m=i>>6, nn=(i&63)*2;
            *(bf162*)&dst[(size_t)(m0+m)*T2+t0+nn]=*(const bf162*)&sOut[m*136+nn];
        }
    } else if constexpr(MODE==M_PROJ){
        for(int i=tid;i<64*128;i+=256){
            int m=i>>7, nn=i&127, t=t0+nn;
            int img=t/49, n=t%49, ch=m0+m;
            float y=xres[((size_t)img*DIMC+ch)*49+n]+ls[ch]*__bfloat162float(sOut[m*136+nn]);
            g_yf[(size_t)ch*T2+t]=y;
            g_yb[(size_t)ch*T2+t]=__float2bfloat16(y);
        }
    } else {
        for(int i=tid;i<64*128;i+=256){
            int m=i>>7, nn=i&127, t=t0+nn;
            int img=t/49, n=t%49, ch=m0+m;
            outp[((size_t)img*DIMC+ch)*49+n]=
                g_yf[(size_t)ch*T2+t]+ls[ch]*__bfloat162float(sOut[m*136+nn]);
        }
    }
}

// ---------------- K1: S = scale*QK^T + bias ---------------------------------
__global__ __launch_bounds__(128) void qk_kernel()
{
    __shared__ bf16 sQ[32*72], sK[32*72];
    const int h=blockIdx.x, img=blockIdx.y;
    const int tid=threadIdx.x, lane=tid&31, warp=tid>>5;
    const int gid=lane>>2, tig=lane&3;
    const size_t base=(size_t)img*49;
    const float scale=0.17677669529663687f;

    for(int i=tid;i<2048;i+=128){
        int c=i>>6, n=i&63;
        bf16 q=__float2bfloat16(0.f), k=q;
        if(n<49){
            q=g_qkv[(size_t)(h*32+c)*T2+base+n];
            k=g_qkv[(size_t)(256+h*32+c)*T2+base+n];
        }
        sQ[c*72+n]=q; sK[c*72+n]=k;
    }
    __syncthreads();
    const int nt=warp;
    uint32_t sqb=smem_u32(sQ), skb=smem_u32(sK);
    float acc[8][4];
    #pragma unroll
    for(int i2=0;i2<8;i2++){ acc[i2][0]=acc[i2][1]=acc[i2][2]=acc[i2][3]=0.f; }
    #pragma unroll
    for(int kk=0;kk<32;kk+=16){
        int rsel=kk+(lane&7)+((lane>>3)&1)*8;
        uint32_t coff=(lane>>4)<<3;
        uint32_t q[4];
        ldsm_x4_t(q, sqb+(rsel*72+nt*16+coff)*2);
        uint32_t A[4]={q[0],q[2],q[1],q[3]};
        #pragma unroll
        for(int mt=0;mt<4;mt++){
            uint32_t kf[4];
            ldsm_x4_t(kf, skb+(rsel*72+mt*16+coff)*2);
            mma_bf16(acc[mt*2],   A, kf[0], kf[1]);
            mma_bf16(acc[mt*2+1], A, kf[2], kf[3]);
        }
    }
    int n1=nt*16+gid, n2=n1+8;
    bf16* Sp=&g_S[((size_t)img*8+h)*4096];
    #pragma unroll
    for(int t8=0;t8<8;t8++){
        int m=t8*8+tig*2;
        float l0=acc[t8][0]*scale, l1=acc[t8][1]*scale;
        float h0=acc[t8][2]*scale, h1=acc[t8][3]*scale;
        if(m<49){
            if(n1<49){ bf162 bb=*(const bf162*)&g_biasx[(h*49+n1)*52+m];
                       l0+=__bfloat162float(bb.x); l1+=__bfloat162float(bb.y); }
            if(n2<49){ bf162 bb=*(const bf162*)&g_biasx[(h*49+n2)*52+m];
                       h0+=__bfloat162float(bb.x); h1+=__bfloat162float(bb.y); }
        }
        *(bf162*)&Sp[n1*64+m]=bf162(__float2bfloat16(l0),__float2bfloat16(l1));
        *(bf162*)&Sp[n2*64+m]=bf162(__float2bfloat16(h0),__float2bfloat16(h1));
    }
}

// ---------------- K2: th1 -> softmax -> th2 -> P (4 CTAs per image) ----------
__global__ __launch_bounds__(128) void mix_kernel(
    const float* __restrict__ th1w, const float* __restrict__ th1b,
    const float* __restrict__ th2w, const float* __restrict__ th2b)
{
    __shared__ bf16 sS[8*13*52];
    __shared__ float sw1[64], sb1[8], sw2[64], sb2[8];
    const int img=blockIdx.x, q=blockIdx.y, tid=threadIdx.x;
    const int n0=q*13;
    const int ncnt=(q==3)?10:13;

    if(tid<64) sw1[tid]=th1w[tid];
    else sw2[tid-64]=th2w[tid-64];
    if(tid<8) sb1[tid]=th1b[tid];
    else if(tid<16) sb2[tid-8]=th2b[tid-8];

    const bf16* Sg=&g_S[(size_t)img*8*4096];
    for(int i=tid;i<8*ncnt*26;i+=128){
        int h=i/(ncnt*26), r=i%(ncnt*26), nl=r/26, mp=(r%26)*2;
        *(bf162*)&sS[(h*13+nl)*52+mp]=*(const bf162*)&Sg[h*4096+(n0+nl)*64+mp];
    }
    __syncthreads();
    for(int i=tid;i<ncnt*26;i+=128){
        int nl=i/26, mp=(i%26)*2;
        float sx[8], sy[8];
        #pragma unroll
        for(int j=0;j<8;j++){
            bf162 v=*(const bf162*)&sS[(j*13+nl)*52+mp];
            sx[j]=__bfloat162float(v.x); sy[j]=__bfloat162float(v.y);
        }
        #pragma unroll
        for(int i2=0;i2<8;i2++){
            float ox=sb1[i2], oy=sb1[i2];
            #pragma unroll
            for(int j=0;j<8;j++){ ox+=sw1[i2*8+j]*sx[j]; oy+=sw1[i2*8+j]*sy[j]; }
            *(bf162*)&sS[(i2*13+nl)*52+mp]=bf162(__float2bfloat16(ox),__float2bfloat16(oy));
        }
    }
    __syncthreads();
    for(int r=tid;r<HEADS*ncnt;r+=128){
        int h=r/ncnt, nl=r%ncnt;
        bf16* rp=&sS[(h*13+nl)*52];
        float mx=-1e30f;
        for(int m=0;m<49;m++) mx=fmaxf(mx,__bfloat162float(rp[m]));
        float su=0.f;
        float ev[49];
        for(int m=0;m<49;m++){ ev[m]=__expf(__bfloat162float(rp[m])-mx); su+=ev[m]; }
        float inv=1.f/su;
        for(int m=0;m<49;m++) rp[m]=__float2bfloat16(ev[m]*inv);
    }
    __syncthreads();
    bf16* Pg=&g_P[(size_t)img*8*4096];
    for(int i=tid;i<ncnt*25;i+=128){
        int nl=i/25, mp=(i%25)*2;
        float sx[8], sy[8];
        #pragma unroll
        for(int j=0;j<8;j++){
            bf162 v=*(const bf162*)&sS[(j*13+nl)*52+mp];
            sx[j]=__bfloat162float(v.x); sy[j]=__bfloat162float(v.y);
        }
        #pragma unroll
        for(int i2=0;i2<8;i2++){
            float ox=sb2[i2], oy=sb2[i2];
            #pragma unroll
            for(int j=0;j<8;j++){ ox+=sw2[i2*8+j]*sx[j]; oy+=sw2[i2*8+j]*sy[j]; }
            if(mp+1>=49) oy=0.f;
            *(bf162*)&Pg[i2*4096+(n0+nl)*64+mp]=bf162(__float2bfloat16(ox),__float2bfloat16(oy));
        }
    }
    for(int i=tid;i<ncnt*7;i+=128){
        int nl=i/7, mp=50+(i%7)*2;
        #pragma unroll
        for(int i2=0;i2<8;i2++)
            *(bf162*)&Pg[i2*4096+(n0+nl)*64+mp]=bf162(__float2bfloat16(0.f),__float2bfloat16(0.f));
    }
}

// ---------------- K3: O = P.V + vloc, relu -----------------------------------
__global__ __launch_bounds__(128) void av_kernel()
{
    __shared__ bf16 sP[64*72], sV[64*136], sO[64*136];
    const int h=blockIdx.x, img=blockIdx.y;
    const int tid=threadIdx.x, lane=tid&31, warp=tid>>5;
    const int gid=lane>>2, tig=lane&3;
    const size_t base=(size_t)img*49;

    const bf16* Pg=&g_P[((size_t)img*8+h)*4096];
    for(int i=tid;i<64*32;i+=128){
        int n=i>>5, mp=(i&31)*2;
        *(bf162*)&sP[n*72+mp]=*(const bf162*)&Pg[n*64+mp];
    }
    for(int i=tid;i<8192;i+=128){
        int d=i>>6, m=i&63;
        bf16 v=__float2bfloat16(0.f);
        if(m<49) v=g_qkv[(size_t)(512+h*128+d)*T2+base+m];
        sV[m*136+d]=v;
    }
    __syncthreads();
    const int nt=warp;
    uint32_t spb=smem_u32(sP), svb=smem_u32(sV);
    float acc[16][4];
    #pragma unroll
    for(int i2=0;i2<16;i2++){ acc[i2][0]=acc[i2][1]=acc[i2][2]=acc[i2][3]=0.f; }
    #pragma unroll
    for(int kk=0;kk<64;kk+=16){
        uint32_t a[4];
        ldsm_x4(a, spb+((nt*16+(lane&15))*72+kk+((lane>>4)<<3))*2);
        #pragma unroll
        for(int ni=0;ni<8;ni++){
            uint32_t bb[4];
            ldsm_x4_t(bb, svb+((kk+(lane&7)+((lane>>3)&1)*8)*136+ni*16+((lane>>4)<<3))*2);
            mma_bf16(acc[ni*2],   a, bb[0], bb[1]);
            mma_bf16(acc[ni*2+1], a, bb[2], bb[3]);
        }
    }
    int n1=nt*16+gid, n2=n1+8;
    #pragma unroll
    for(int t16=0;t16<16;t16++){
        int d=t16*8+tig*2;
        *(bf162*)&sO[n1*136+d]=bf162(__float2bfloat16(acc[t16][0]),__float2bfloat16(acc[t16][1]));
        *(bf162*)&sO[n2*136+d]=bf162(__float2bfloat16(acc[t16][2]),__float2bfloat16(acc[t16][3]));
    }
    __syncthreads();
    for(int i=tid;i<8192;i+=128){
        int d=i>>6, n=i&63;
        if(n<NTOK){
            int ch=h*128+d;
            float o=__bfloat162float(sO[n*136+d])
                   +__bfloat162float(g_vloc[(size_t)ch*T2+base+n]);
            g_attn[(size_t)ch*T2+base+n]=__float2bfloat16(fmaxf(o,0.f));
        }
    }
}

// ---------------- launch ----------------------------------------------------
extern "C" void kernel_launch(void* const* d_in, const int* in_sizes, int n_in,
                              void* d_out, int out_size)
{
    const float *x=(const float*)d_in[0], *q_w=(const float*)d_in[1], *q_b=(const float*)d_in[2];
    const float *k_w=(const float*)d_in[3], *k_b=(const float*)d_in[4];
    const float *v_w=(const float*)d_in[5], *v_b=(const float*)d_in[6];
    const float *lv_w=(const float*)d_in[7], *lv_b=(const float*)d_in[8];
    const float *th1_w=(const float*)d_in[9], *th1_b=(const float*)d_in[10];
    const float *th2_w=(const float*)d_in[11], *th2_b=(const float*)d_in[12];
    const float *attn_b=(const float*)d_in[13];
    const float *proj_w=(const float*)d_in[14], *proj_b=(const float*)d_in[15];
    const float *fc1_w=(const float*)d_in[16], *fc1_b=(const float*)d_in[17];
    const float *mid_w=(const float*)d_in[18], *mid_b=(const float*)d_in[19];
    const float *fc2_w=(const float*)d_in[20], *fc2_b=(const float*)d_in[21];
    const float *ls1=(const float*)d_in[22], *ls2=(const float*)d_in[23];
    const int* bidx=(const int*)d_in[24];
    float* outp=(float*)d_out;

    cudaFuncSetAttribute(gemm64<M_QKV,384>,  cudaFuncAttributeMaxDynamicSharedMemorySize, G64_SMEM);
    cudaFuncSetAttribute(gemm64<M_FC1,384>,  cudaFuncAttributeMaxDynamicSharedMemorySize, G64_SMEM);
    cudaFuncSetAttribute(gemm64<M_PROJ,1024>, cudaFuncAttributeMaxDynamicSharedMemorySize, G64_SMEM);
    cudaFuncSetAttribute(gemm64<M_FC2,1536>,  cudaFuncAttributeMaxDynamicSharedMemorySize, G64_SMEM);

    const int NT=98;   // T2/128
    prologue<<<(int)((PTOTAL+255)/256),256>>>(q_w,k_w,v_w,q_b,k_b,v_b,proj_w,fc1_w,fc2_w,x);
    bias_expand<<<(HEADS*49*52+255)/256,256>>>(attn_b,bidx);
    gemm64<M_QKV,384><<<dim3(QKVC/64,NT),256,G64_SMEM>>>(nullptr,nullptr,nullptr,nullptr);
    dw_kernel<0><<<DHCH*2,128>>>(lv_w, lv_b);
    qk_kernel<<<dim3(HEADS,BATCH),128>>>();
    mix_kernel<<<dim3(BATCH,4),128>>>(th1_w,th1_b,th2_w,th2_b);
    av_kernel<<<dim3(HEADS,BATCH),128>>>();
    gemm64<M_PROJ,1024><<<dim3(DIMC/64,NT),256,G64_SMEM>>>(proj_b,x,ls1,nullptr);
    gemm64<M_FC1,384><<<dim3(HID/64,NT),256,G64_SMEM>>>(fc1_b,nullptr,nullptr,nullptr);
    dw_kernel<1><<<HID*2,128>>>(mid_w, mid_b);
    gemm64<M_FC2,1536><<<dim3(DIMC/64,NT),256,G64_SMEM>>>(fc2_b,nullptr,ls2,outp);
}

// round 17
// speedup vs baseline: 1.0557x; 1.0557x over previous
#include <cuda_runtime.h>
#include <cuda_bf16.h>
#include <cstdint>

#define DEV_INLINE __device__ __forceinline__
constexpr int BATCH=256, DIMC=384, NTOK=49;
constexpr int T2=BATCH*NTOK;            // 12544 dense tokens = 98*128
constexpr int HEADS=8, DVAL=128, DHCH=1024, HID=1536, QKVC=1536;
typedef __nv_bfloat16 bf16;
typedef __nv_bfloat162 bf162;

__device__ bf16  g_wqkv[QKVC*DIMC], g_wproj[DIMC*DHCH];
__device__ bf16  g_wfc1[HID*DIMC],  g_wfc2[DIMC*HID];
__device__ float g_bqkv[QKVC];
__device__ bf16  g_xt [DIMC*T2];
__device__ bf16  g_qkv[QKVC*T2], g_vloc[DHCH*T2], g_attn[DHCH*T2];
__device__ float g_yf [DIMC*T2];
__device__ bf16  g_yb [DIMC*T2], g_h1[HID*T2], g_h2[HID*T2];
__device__ bf16  g_biasx[HEADS*49*52];
__device__ bf16  g_S[(size_t)BATCH*HEADS*64*64];
__device__ bf16  g_P[(size_t)BATCH*HEADS*64*64];   // rows n>=49 stay zero

DEV_INLINE uint32_t smem_u32(const void* p){ return (uint32_t)__cvta_generic_to_shared(p); }
DEV_INLINE void cp16(void* s, const void* g){
    asm volatile("cp.async.ca.shared.global [%0], [%1], 16;\n"::"r"(smem_u32(s)),"l"(g)); }
DEV_INLINE void cp_commit(){ asm volatile("cp.async.commit_group;\n"); }
DEV_INLINE void cp_wait2(){ asm volatile("cp.async.wait_group 2;\n"); }
DEV_INLINE void ldsm_x4(uint32_t r[4], uint32_t a){
    asm volatile("ldmatrix.sync.aligned.m8n8.x4.shared.b16 {%0,%1,%2,%3}, [%4];\n"
        :"=r"(r[0]),"=r"(r[1]),"=r"(r[2]),"=r"(r[3]):"r"(a)); }
DEV_INLINE void ldsm_x4_t(uint32_t r[4], uint32_t a){
    asm volatile("ldmatrix.sync.aligned.m8n8.x4.trans.shared.b16 {%0,%1,%2,%3}, [%4];\n"
        :"=r"(r[0]),"=r"(r[1]),"=r"(r[2]),"=r"(r[3]):"r"(a)); }
DEV_INLINE void mma_bf16(float c[4], const uint32_t a[4], uint32_t b0, uint32_t b1){
    asm volatile("mma.sync.aligned.m16n8k16.row.col.f32.bf16.bf16.f32 "
        "{%0,%1,%2,%3},{%4,%5,%6,%7},{%8,%9},{%0,%1,%2,%3};\n"
        :"+f"(c[0]),"+f"(c[1]),"+f"(c[2]),"+f"(c[3])
        :"r"(a[0]),"r"(a[1]),"r"(a[2]),"r"(a[3]),"r"(b0),"r"(b1)); }

// ---------------- prologue ---------------------------------------------------
constexpr int W1=256*384, W3=1024*384, WP=384*1024, WF=1536*384;
constexpr long PTOTAL=(long)W1*2+W3+WP+WF*2+1536+(long)DIMC*T2;
__global__ void prologue(const float* qw,const float* kw,const float* vw,
                         const float* qb,const float* kb,const float* vb,
                         const float* pw,const float* f1w,const float* f2w,const float* x){
    long i=(long)blockIdx.x*blockDim.x+threadIdx.x;
    if(i>=PTOTAL) return;
    if(i<W1){ g_wqkv[i]=__float2bfloat16(qw[i]); return;} i-=W1;
    if(i<W1){ g_wqkv[W1+i]=__float2bfloat16(kw[i]); return;} i-=W1;
    if(i<W3){ g_wqkv[2*W1+i]=__float2bfloat16(vw[i]); return;} i-=W3;
    if(i<WP){ g_wproj[i]=__float2bfloat16(pw[i]); return;} i-=WP;
    if(i<WF){ g_wfc1[i]=__float2bfloat16(f1w[i]); return;} i-=WF;
    if(i<WF){ g_wfc2[i]=__float2bfloat16(f2w[i]); return;} i-=WF;
    if(i<256){ g_bqkv[i]=qb[i]; return;} i-=256;
    if(i<256){ g_bqkv[256+i]=kb[i]; return;} i-=256;
    if(i<1024){ g_bqkv[512+i]=vb[i]; return;} i-=1024;
    int c=(int)(i/T2), t=(int)(i%T2);
    int img=t/49, n=t%49;
    g_xt[i]=__float2bfloat16(x[((size_t)img*DIMC+c)*49+n]);
}
__global__ void bias_expand(const float* attn_bias, const int* bias_idxs){
    int i=blockIdx.x*blockDim.x+threadIdx.x;
    if(i>=HEADS*49*52) return;
    int h=i/(49*52), r=i%(49*52), n=r/52, m=r%52;
    float v=(m<49)? attn_bias[h*49+bias_idxs[n*49+m]] : 0.f;
    g_biasx[i]=__float2bfloat16(v);
}

// ---------------- depthwise 3x3: CTA = 128 images of ONE channel -------------
template<int WHICH>
__global__ __launch_bounds__(128) void dw_kernel(
    const float* __restrict__ w9, const float* __restrict__ b9){
    __shared__ bf16 sin [128*49];
    __shared__ bf16 sout[128*49];
    const int blk=blockIdx.x, ch=blk>>1, half=blk&1;
    const int tid=threadIdx.x;
    const bf16* in  = ((WHICH==0)? (g_qkv+(size_t)512*T2) : g_h1)
                      + (size_t)ch*T2 + (size_t)half*6272;
    bf16*       out = ((WHICH==0)? g_vloc : g_h2)
                      + (size_t)ch*T2 + (size_t)half*6272;

    for(int i=tid;i<3136;i+=128) ((bf162*)sin)[i]=((const bf162*)in)[i];
    float w[9];
    #pragma unroll
    for(int k=0;k<9;k++) w[k]=__ldg(&w9[ch*9+k]);
    const float bb=__ldg(&b9[ch]);
    __syncthreads();

    const bf16* v=&sin[tid*49];
    bf16* o=&sout[tid*49];
    #pragma unroll
    for(int pi=0;pi<7;pi++){
        #pragma unroll
        for(int pj=0;pj<7;pj++){
            float s=bb;
            #pragma unroll
            for(int di=-1;di<=1;di++){
                if(pi+di<0||pi+di>6) continue;
                #pragma unroll
                for(int dj=-1;dj<=1;dj++){
                    if(pj+dj<0||pj+dj>6) continue;
                    s+=w[(di+1)*3+(dj+1)]*__bfloat162float(v[(pi+di)*7+(pj+dj)]);
                }
            }
            if(WHICH==1) s=fmaxf(s,0.f);
            o[pi*7+pj]=__float2bfloat16(s);
        }
    }
    __syncthreads();
    for(int i=tid;i<3136;i+=128) ((bf162*)out)[i]=((const bf162*)sout)[i];
}

// ---------------- gemm128: BM=128 (QKV, FC1) --------------------------------
enum { M_QKV=0, M_PROJ=1, M_FC1=2, M_FC2=3 };
constexpr int SA_ELEM=128*40, SB_ELEM=32*136;
constexpr int STAGE_BYTES=(SA_ELEM+SB_ELEM)*2;
constexpr int NSTG=4;
constexpr int GEMM_SMEM=NSTG*STAGE_BYTES;

template<int K>
DEV_INLINE void load_stage(char* sm,int s,int k0,int m0,int t0,int tid,
                           const bf16* __restrict__ A,const bf16* __restrict__ Bm){
    bf16* sA=(bf16*)(sm+s*STAGE_BYTES);
    bf16* sB=(bf16*)(sm+s*STAGE_BYTES+SA_ELEM*2);
    #pragma unroll
    for(int i=0;i<2;i++){ int c=tid+i*256, row=c>>2, part=c&3;
        cp16(&sA[row*40+part*8], &A[(size_t)(m0+row)*K+k0+part*8]); }
    #pragma unroll
    for(int i=0;i<2;i++){ int c=tid+i*256, row=c>>4, part=c&15;
        cp16(&sB[row*136+part*8], &Bm[(size_t)(k0+row)*T2+t0+part*8]); }
}

template<int MODE,int K>
__global__ __launch_bounds__(256) void gemm128(const float* __restrict__ bias)
{
    extern __shared__ char sm[];
    const int m0=blockIdx.x*128, t0=blockIdx.y*128;
    const int tid=threadIdx.x, lane=tid&31, warp=tid>>5;
    const int m0w=(warp>>1)*32, n0w=(warp&1)*64;
    const int gid=lane>>2, tig=lane&3;
    const bf16 *A, *Bm;
    if constexpr(MODE==M_QKV){ A=g_wqkv; Bm=g_xt; }
    else { A=g_wfc1; Bm=g_yb; }

    float acc[2][8][4];
    #pragma unroll
    for(int mi=0;mi<2;mi++)
        #pragma unroll
        for(int nj=0;nj<8;nj++){ acc[mi][nj][0]=acc[mi][nj][1]=acc[mi][nj][2]=acc[mi][nj][3]=0.f; }

    constexpr int KT=K/32;
    load_stage<K>(sm,0,0,m0,t0,tid,A,Bm);  cp_commit();
    load_stage<K>(sm,1,32,m0,t0,tid,A,Bm); cp_commit();
    load_stage<K>(sm,2,64,m0,t0,tid,A,Bm); cp_commit();
    for(int it=0;it<KT;++it){
        cp_wait2(); __syncthreads();
        const bf16* sA=(const bf16*)(sm+(it%NSTG)*STAGE_BYTES);
        const bf16* sB=(const bf16*)(sm+(it%NSTG)*STAGE_BYTES+SA_ELEM*2);
        #pragma unroll
        for(int kk=0;kk<32;kk+=16){
            uint32_t a[2][4], bfr[4][4];
            #pragma unroll
            for(int mi=0;mi<2;mi++)
                ldsm_x4(a[mi], smem_u32(&sA[(m0w+mi*16+(lane&15))*40+kk+((lane>>4)<<3)]));
            #pragma unroll
            for(int ni=0;ni<4;ni++)
                ldsm_x4_t(bfr[ni], smem_u32(&sB[(kk+(lane&7)+((lane>>3)&1)*8)*136+n0w+ni*16+((lane>>4)<<3)]));
            #pragma unroll
            for(int mi=0;mi<2;mi++)
                #pragma unroll
                for(int nj=0;nj<8;nj++)
                    mma_bf16(acc[mi][nj], a[mi], bfr[nj>>1][(nj&1)?2:0], bfr[nj>>1][(nj&1)?3:1]);
        }
        if(it+3<KT) load_stage<K>(sm,(it+3)%NSTG,(it+3)*32,m0,t0,tid,A,Bm);
        cp_commit();
    }
    __syncthreads();
    bf16* sOut=(bf16*)sm;
    float bs[2][2];
    #pragma unroll
    for(int mi=0;mi<2;mi++){
        int r=m0+m0w+mi*16+gid;
        if constexpr(MODE==M_QKV){ bs[mi][0]=g_bqkv[r]; bs[mi][1]=g_bqkv[r+8]; }
        else { bs[mi][0]=bias[r]; bs[mi][1]=bias[r+8]; }
    }
    #pragma unroll
    for(int mi=0;mi<2;mi++)
        #pragma unroll
        for(int nj=0;nj<8;nj++){
            int mrow=m0w+mi*16+gid, ncol=n0w+nj*8+tig*2;
            float v0=acc[mi][nj][0]+bs[mi][0], v1=acc[mi][nj][1]+bs[mi][0];
            float v2=acc[mi][nj][2]+bs[mi][1], v3=acc[mi][nj][3]+bs[mi][1];
            if constexpr(MODE==M_FC1){ v0=fmaxf(v0,0.f); v1=fmaxf(v1,0.f); v2=fmaxf(v2,0.f); v3=fmaxf(v3,0.f); }
            *(bf162*)&sOut[mrow*136+ncol]=bf162(__float2bfloat16(v0),__float2bfloat16(v1));
            *(bf162*)&sOut[(mrow+8)*136+ncol]=bf162(__float2bfloat16(v2),__float2bfloat16(v3));
        }
    __syncthreads();
    bf16* dst = (MODE==M_QKV)? g_qkv : g_h1;
    for(int i=tid;i<8192;i+=256){
        int m=i>>6, nn=(i&63)*2;
        *(bf162*)&dst[(size_t)(m0+m)*T2+t0+nn]=*(const bf162*)&sOut[m*136+nn];
    }
}

// ---------------- gemm64k: BM=64 (PROJ, FC2) ---------------------------------
constexpr int SA64=64*40, SB64=32*136;
constexpr int STG64=(SA64+SB64)*2;
constexpr int G64_SMEM=NSTG*STG64;

template<int K>
DEV_INLINE void load_stage64(char* sm,int s,int k0,int m0,int t0,int tid,
                             const bf16* __restrict__ A,const bf16* __restrict__ Bm){
    bf16* sA=(bf16*)(sm+s*STG64);
    bf16* sB=(bf16*)(sm+s*STG64+SA64*2);
    { int row=tid>>2, part=tid&3;
      cp16(&sA[row*40+part*8], &A[(size_t)(m0+row)*K+k0+part*8]); }
    #pragma unroll
    for(int i=0;i<2;i++){ int c=tid+i*256, row=c>>4, part=c&15;
        cp16(&sB[row*136+part*8], &Bm[(size_t)(k0+row)*T2+t0+part*8]); }
}

template<int MODE,int K>
__global__ __launch_bounds__(256) void gemm64k(
    const float* __restrict__ bias, const float* __restrict__ xres,
    const float* __restrict__ ls,   float* __restrict__ outp)
{
    extern __shared__ char sm[];
    const int m0=blockIdx.x*64, t0=blockIdx.y*128;
    const int tid=threadIdx.x, lane=tid&31, warp=tid>>5;
    const int m0w=(warp>>2)*32, n0w=(warp&3)*32;
    const int gid=lane>>2, tig=lane&3;
    const bf16 *A, *Bm;
    if constexpr(MODE==M_PROJ){ A=g_wproj; Bm=g_attn; }
    else { A=g_wfc2; Bm=g_h2; }

    float acc[2][4][4];
    #pragma unroll
    for(int mi=0;mi<2;mi++)
        #pragma unroll
        for(int nj=0;nj<4;nj++){ acc[mi][nj][0]=acc[mi][nj][1]=acc[mi][nj][2]=acc[mi][nj][3]=0.f; }

    constexpr int KT=K/32;
    load_stage64<K>(sm,0,0,m0,t0,tid,A,Bm);  cp_commit();
    load_stage64<K>(sm,1,32,m0,t0,tid,A,Bm); cp_commit();
    load_stage64<K>(sm,2,64,m0,t0,tid,A,Bm); cp_commit();
    for(int it=0;it<KT;++it){
        cp_wait2(); __syncthreads();
        const bf16* sA=(const bf16*)(sm+(it%NSTG)*STG64);
        const bf16* sB=(const bf16*)(sm+(it%NSTG)*STG64+SA64*2);
        #pragma unroll
        for(int kk=0;kk<32;kk+=16){
            uint32_t a[2][4], bfr[2][4];
            #pragma unroll
            for(int mi=0;mi<2;mi++)
                ldsm_x4(a[mi], smem_u32(&sA[(m0w+mi*16+(lane&15))*40+kk+((lane>>4)<<3)]));
            #pragma unroll
            for(int ni=0;ni<2;ni++)
                ldsm_x4_t(bfr[ni], smem_u32(&sB[(kk+(lane&7)+((lane>>3)&1)*8)*136+n0w+ni*16+((lane>>4)<<3)]));
            #pragma unroll
            for(int mi=0;mi<2;mi++)
                #pragma unroll
                for(int nj=0;nj<4;nj++)
                    mma_bf16(acc[mi][nj], a[mi], bfr[nj>>1][(nj&1)?2:0], bfr[nj>>1][(nj&1)?3:1]);
        }
        if(it+3<KT) load_stage64<K>(sm,(it+3)%NSTG,(it+3)*32,m0,t0,tid,A,Bm);
        cp_commit();
    }
    __syncthreads();
    bf16* sOut=(bf16*)sm;
    float bs[2][2];
    #pragma unroll
    for(int mi=0;mi<2;mi++){
        int r=m0+m0w+mi*16+gid;
        bs[mi][0]=bias[r]; bs[mi][1]=bias[r+8];
    }
    #pragma unroll
    for(int mi=0;mi<2;mi++)
        #pragma unroll
        for(int nj=0;nj<4;nj++){
            int mrow=m0w+mi*16+gid, ncol=n0w+nj*8+tig*2;
            float v0=acc[mi][nj][0]+bs[mi][0], v1=acc[mi][nj][1]+bs[mi][0];
            float v2=acc[mi][nj][2]+bs[mi][1], v3=acc[mi][nj][3]+bs[mi][1];
            *(bf162*)&sOut[mrow*136+ncol]=bf162(__float2bfloat16(v0),__float2bfloat16(v1));
            *(bf162*)&sOut[(mrow+8)*136+ncol]=bf162(__float2bfloat16(v2),__float2bfloat16(v3));
        }
    __syncthreads();

    if constexpr(MODE==M_PROJ){
        for(int i=tid;i<64*128;i+=256){
            int m=i>>7, nn=i&127, t=t0+nn;
            int img=t/49, n=t%49, ch=m0+m;
            float y=xres[((size_t)img*DIMC+ch)*49+n]+ls[ch]*__bfloat162float(sOut[m*136+nn]);
            g_yf[(size_t)ch*T2+t]=y;
            g_yb[(size_t)ch*T2+t]=__float2bfloat16(y);
        }
    } else {
        for(int i=tid;i<64*128;i+=256){
            int m=i>>7, nn=i&127, t=t0+nn;
            int img=t/49, n=t%49, ch=m0+m;
            outp[((size_t)img*DIMC+ch)*49+n]=
                g_yf[(size_t)ch*T2+t]+ls[ch]*__bfloat162float(sOut[m*136+nn]);
        }
    }
}

// ---------------- K1: S = scale*QK^T + bias ---------------------------------
__global__ __launch_bounds__(128) void qk_kernel()
{
    __shared__ bf16 sQ[32*72], sK[32*72];
    const int h=blockIdx.x, img=blockIdx.y;
    const int tid=threadIdx.x, lane=tid&31, warp=tid>>5;
    const int gid=lane>>2, tig=lane&3;
    const size_t base=(size_t)img*49;
    const float scale=0.17677669529663687f;

    for(int i=tid;i<2048;i+=128){
        int c=i>>6, n=i&63;
        bf16 q=__float2bfloat16(0.f), k=q;
        if(n<49){
            q=g_qkv[(size_t)(h*32+c)*T2+base+n];
            k=g_qkv[(size_t)(256+h*32+c)*T2+base+n];
        }
        sQ[c*72+n]=q; sK[c*72+n]=k;
    }
    __syncthreads();
    const int nt=warp;
    uint32_t sqb=smem_u32(sQ), skb=smem_u32(sK);
    float acc[8][4];
    #pragma unroll
    for(int i2=0;i2<8;i2++){ acc[i2][0]=acc[i2][1]=acc[i2][2]=acc[i2][3]=0.f; }
    #pragma unroll
    for(int kk=0;kk<32;kk+=16){
        int rsel=kk+(lane&7)+((lane>>3)&1)*8;
        uint32_t coff=(lane>>4)<<3;
        uint32_t q[4];
        ldsm_x4_t(q, sqb+(rsel*72+nt*16+coff)*2);
        uint32_t A[4]={q[0],q[2],q[1],q[3]};
        #pragma unroll
        for(int mt=0;mt<4;mt++){
            uint32_t kf[4];
            ldsm_x4_t(kf, skb+(rsel*72+mt*16+coff)*2);
            mma_bf16(acc[mt*2],   A, kf[0], kf[1]);
            mma_bf16(acc[mt*2+1], A, kf[2], kf[3]);
        }
    }
    int n1=nt*16+gid, n2=n1+8;
    bf16* Sp=&g_S[((size_t)img*8+h)*4096];
    #pragma unroll
    for(int t8=0;t8<8;t8++){
        int m=t8*8+tig*2;
        float l0=acc[t8][0]*scale, l1=acc[t8][1]*scale;
        float h0=acc[t8][2]*scale, h1=acc[t8][3]*scale;
        if(m<49){
            if(n1<49){ bf162 bb=*(const bf162*)&g_biasx[(h*49+n1)*52+m];
                       l0+=__bfloat162float(bb.x); l1+=__bfloat162float(bb.y); }
            if(n2<49){ bf162 bb=*(const bf162*)&g_biasx[(h*49+n2)*52+m];
                       h0+=__bfloat162float(bb.x); h1+=__bfloat162float(bb.y); }
        }
        *(bf162*)&Sp[n1*64+m]=bf162(__float2bfloat16(l0),__float2bfloat16(l1));
        *(bf162*)&Sp[n2*64+m]=bf162(__float2bfloat16(h0),__float2bfloat16(h1));
    }
}

// ---------------- K2: th1 -> softmax -> th2 -> P (4 CTAs per image) ----------
__global__ __launch_bounds__(128) void mix_kernel(
    const float* __restrict__ th1w, const float* __restrict__ th1b,
    const float* __restrict__ th2w, const float* __restrict__ th2b)
{
    __shared__ bf16 sS[8*13*52];
    __shared__ float sw1[64], sb1[8], sw2[64], sb2[8];
    const int img=blockIdx.x, q=blockIdx.y, tid=threadIdx.x;
    const int n0=q*13;
    const int ncnt=(q==3)?10:13;

    if(tid<64) sw1[tid]=th1w[tid];
    else sw2[tid-64]=th2w[tid-64];
    if(tid<8) sb1[tid]=th1b[tid];
    else if(tid<16) sb2[tid-8]=th2b[tid-8];

    const bf16* Sg=&g_S[(size_t)img*8*4096];
    for(int i=tid;i<8*ncnt*26;i+=128){
        int h=i/(ncnt*26), r=i%(ncnt*26), nl=r/26, mp=(r%26)*2;
        *(bf162*)&sS[(h*13+nl)*52+mp]=*(const bf162*)&Sg[h*4096+(n0+nl)*64+mp];
    }
    __syncthreads();
    for(int i=tid;i<ncnt*26;i+=128){
        int nl=i/26, mp=(i%26)*2;
        float sx[8], sy[8];
        #pragma unroll
        for(int j=0;j<8;j++){
            bf162 v=*(const bf162*)&sS[(j*13+nl)*52+mp];
            sx[j]=__bfloat162float(v.x); sy[j]=__bfloat162float(v.y);
        }
        #pragma unroll
        for(int i2=0;i2<8;i2++){
            float ox=sb1[i2], oy=sb1[i2];
            #pragma unroll
            for(int j=0;j<8;j++){ ox+=sw1[i2*8+j]*sx[j]; oy+=sw1[i2*8+j]*sy[j]; }
            *(bf162*)&sS[(i2*13+nl)*52+mp]=bf162(__float2bfloat16(ox),__float2bfloat16(oy));
        }
    }
    __syncthreads();
    for(int r=tid;r<HEADS*ncnt;r+=128){
        int h=r/ncnt, nl=r%ncnt;
        bf16* rp=&sS[(h*13+nl)*52];
        float mx=-1e30f;
        for(int m=0;m<49;m++) mx=fmaxf(mx,__bfloat162float(rp[m]));
        float su=0.f;
        float ev[49];
        for(int m=0;m<49;m++){ ev[m]=__expf(__bfloat162float(rp[m])-mx); su+=ev[m]; }
        float inv=1.f/su;
        for(int m=0;m<49;m++) rp[m]=__float2bfloat16(ev[m]*inv);
    }
    __syncthreads();
    bf16* Pg=&g_P[(size_t)img*8*4096];
    for(int i=tid;i<ncnt*25;i+=128){
        int nl=i/25, mp=(i%25)*2;
        float sx[8], sy[8];
        #pragma unroll
        for(int j=0;j<8;j++){
            bf162 v=*(const bf162*)&sS[(j*13+nl)*52+mp];
            sx[j]=__bfloat162float(v.x); sy[j]=__bfloat162float(v.y);
        }
        #pragma unroll
        for(int i2=0;i2<8;i2++){
            float ox=sb2[i2], oy=sb2[i2];
            #pragma unroll
            for(int j=0;j<8;j++){ ox+=sw2[i2*8+j]*sx[j]; oy+=sw2[i2*8+j]*sy[j]; }
            if(mp+1>=49) oy=0.f;
            *(bf162*)&Pg[i2*4096+(n0+nl)*64+mp]=bf162(__float2bfloat16(ox),__float2bfloat16(oy));
        }
    }
    for(int i=tid;i<ncnt*7;i+=128){
        int nl=i/7, mp=50+(i%7)*2;
        #pragma unroll
        for(int i2=0;i2<8;i2++)
            *(bf162*)&Pg[i2*4096+(n0+nl)*64+mp]=bf162(__float2bfloat16(0.f),__float2bfloat16(0.f));
    }
}

// ---------------- K3: O = P.V + vloc, relu -----------------------------------
__global__ __launch_bounds__(128) void av_kernel()
{
    __shared__ bf16 sP[64*72], sV[64*136], sO[64*136];
    const int h=blockIdx.x, img=blockIdx.y;
    const int tid=threadIdx.x, lane=tid&31, warp=tid>>5;
    const int gid=lane>>2, tig=lane&3;
    const size_t base=(size_t)img*49;

    const bf16* Pg=&g_P[((size_t)img*8+h)*4096];
    for(int i=tid;i<64*32;i+=128){
        int n=i>>5, mp=(i&31)*2;
        *(bf162*)&sP[n*72+mp]=*(const bf162*)&Pg[n*64+mp];
    }
    for(int i=tid;i<8192;i+=128){
        int d=i>>6, m=i&63;
        bf16 v=__float2bfloat16(0.f);
        if(m<49) v=g_qkv[(size_t)(512+h*128+d)*T2+base+m];
        sV[m*136+d]=v;
    }
    __syncthreads();
    const int nt=warp;
    uint32_t spb=smem_u32(sP), svb=smem_u32(sV);
    float acc[16][4];
    #pragma unroll
    for(int i2=0;i2<16;i2++){ acc[i2][0]=acc[i2][1]=acc[i2][2]=acc[i2][3]=0.f; }
    #pragma unroll
    for(int kk=0;kk<64;kk+=16){
        uint32_t a[4];
        ldsm_x4(a, spb+((nt*16+(lane&15))*72+kk+((lane>>4)<<3))*2);
        #pragma unroll
        for(int ni=0;ni<8;ni++){
            uint32_t bb[4];
            ldsm_x4_t(bb, svb+((kk+(lane&7)+((lane>>3)&1)*8)*136+ni*16+((lane>>4)<<3))*2);
            mma_bf16(acc[ni*2],   a, bb[0], bb[1]);
            mma_bf16(acc[ni*2+1], a, bb[2], bb[3]);
        }
    }
    int n1=nt*16+gid, n2=n1+8;
    #pragma unroll
    for(int t16=0;t16<16;t16++){
        int d=t16*8+tig*2;
        *(bf162*)&sO[n1*136+d]=bf162(__float2bfloat16(acc[t16][0]),__float2bfloat16(acc[t16][1]));
        *(bf162*)&sO[n2*136+d]=bf162(__float2bfloat16(acc[t16][2]),__float2bfloat16(acc[t16][3]));
    }
    __syncthreads();
    for(int i=tid;i<8192;i+=128){
        int d=i>>6, n=i&63;
        if(n<NTOK){
            int ch=h*128+d;
            float o=__bfloat162float(sO[n*136+d])
                   +__bfloat162float(g_vloc[(size_t)ch*T2+base+n]);
            g_attn[(size_t)ch*T2+base+n]=__float2bfloat16(fmaxf(o,0.f));
        }
    }
}

// ---------------- launch ----------------------------------------------------
extern "C" void kernel_launch(void* const* d_in, const int* in_sizes, int n_in,
                              void* d_out, int out_size)
{
    const float *x=(const float*)d_in[0], *q_w=(const float*)d_in[1], *q_b=(const float*)d_in[2];
    const float *k_w=(const float*)d_in[3], *k_b=(const float*)d_in[4];
    const float *v_w=(const float*)d_in[5], *v_b=(const float*)d_in[6];
    const float *lv_w=(const float*)d_in[7], *lv_b=(const float*)d_in[8];
    const float *th1_w=(const float*)d_in[9], *th1_b=(const float*)d_in[10];
    const float *th2_w=(const float*)d_in[11], *th2_b=(const float*)d_in[12];
    const float *attn_b=(const float*)d_in[13];
    const float *proj_w=(const float*)d_in[14], *proj_b=(const float*)d_in[15];
    const float *fc1_w=(const float*)d_in[16], *fc1_b=(const float*)d_in[17];
    const float *mid_w=(const float*)d_in[18], *mid_b=(const float*)d_in[19];
    const float *fc2_w=(const float*)d_in[20], *fc2_b=(const float*)d_in[21];
    const float *ls1=(const float*)d_in[22], *ls2=(const float*)d_in[23];
    const int* bidx=(const int*)d_in[24];
    float* outp=(float*)d_out;

    cudaFuncSetAttribute(gemm128<M_QKV,384>,  cudaFuncAttributeMaxDynamicSharedMemorySize, GEMM_SMEM);
    cudaFuncSetAttribute(gemm128<M_FC1,384>,  cudaFuncAttributeMaxDynamicSharedMemorySize, GEMM_SMEM);
    cudaFuncSetAttribute(gemm64k<M_PROJ,1024>, cudaFuncAttributeMaxDynamicSharedMemorySize, G64_SMEM);
    cudaFuncSetAttribute(gemm64k<M_FC2,1536>,  cudaFuncAttributeMaxDynamicSharedMemorySize, G64_SMEM);

    const int NT=98;   // T2/128
    prologue<<<(int)((PTOTAL+255)/256),256>>>(q_w,k_w,v_w,q_b,k_b,v_b,proj_w,fc1_w,fc2_w,x);
    bias_expand<<<(HEADS*49*52+255)/256,256>>>(attn_b,bidx);
    gemm128<M_QKV,384><<<dim3(QKVC/128,NT),256,GEMM_SMEM>>>(nullptr);
    dw_kernel<0><<<DHCH*2,128>>>(lv_w, lv_b);
    qk_kernel<<<dim3(HEADS,BATCH),128>>>();
    mix_kernel<<<dim3(BATCH,4),128>>>(th1_w,th1_b,th2_w,th2_b);
    av_kernel<<<dim3(HEADS,BATCH),128>>>();
    gemm64k<M_PROJ,1024><<<dim3(DIMC/64,NT),256,G64_SMEM>>>(proj_b,x,ls1,nullptr);
    gemm128<M_FC1,384><<<dim3(HID/128,NT),256,GEMM_SMEM>>>(fc1_b);
    dw_kernel<1><<<HID*2,128>>>(mid_w, mid_b);
    gemm64k<M_FC2,1536><<<dim3(DIMC/64,NT),256,G64_SMEM>>>(fc2_b,nullptr,ls2,outp);
}